// round 13
// baseline (speedup 1.0000x reference)
#include <cuda_runtime.h>
#include <math.h>
#include <float.h>

// Problem constants
#define NB     262144
#define DDIM   256
#define HDIM   256
#define EDIM   5

// Tiling: 64 rows per CTA, 256 threads, thread tile = 16 rows x 4 cols
// (rows packed in pairs inside f32x2 accumulators -> acc[8][4] u64 = 64 regs)
#define TILE_M   64
#define TILE_K   32
#define NTHREADS 256

// Shared memory layout (floats).
// xs: transposed x tile [TILE_K][XT_STRIDE]  (xs[k][row], NOT duplicated)
// ws: W1 tile [TILE_K][HDIM]
// hs: 64-row h tile for epilogue (overlaps xs/ws)
#define XT_STRIDE 68                          // 64 rows + 4 pad; 68*4=272 -> every k-row 16B-aligned
#define WS_OFF    (TILE_K * XT_STRIDE)        // 2176
#define STAGE_FLOATS (WS_OFF + TILE_K * HDIM) // 10368
#define HS_STRIDE 264
#define HS_FLOATS (TILE_M * HS_STRIDE)        // 16896 (> staging; hs owns [0,16896))
#define W2_OFF    HS_FLOATS
#define B1_OFF    (W2_OFF + HDIM * EDIM)
#define B2_OFF    (B1_OFF + HDIM)
#define SMEM_FLOATS (B2_OFF + 8)
#define SMEM_BYTES  (SMEM_FLOATS * 4)         // 73760 bytes -> 2 CTAs/SM

__device__ __forceinline__ void fma2(unsigned long long& d,
                                     unsigned long long a,
                                     unsigned long long b) {
    // packed 2x fp32 FMA (each half is an exact fp32 fma) — sm_100+ PTX only
    asm("fma.rn.f32x2 %0, %1, %2, %0;" : "+l"(d) : "l"(a), "l"(b));
}

__device__ __forceinline__ unsigned long long dup2(float v) {
    unsigned int u = __float_as_uint(v);
    return ((unsigned long long)u << 32) | (unsigned long long)u;
}

extern __shared__ float smem[];

__global__ void __launch_bounds__(NTHREADS, 2)
router_gating_kernel(const float* __restrict__ x,
                     const float* __restrict__ W1,
                     const float* __restrict__ b1,
                     const float* __restrict__ W2,
                     const float* __restrict__ b2,
                     float* __restrict__ out,
                     int write_idx)
{
    float* xs  = smem;                 // [TILE_K][XT_STRIDE] transposed x
    float* ws  = smem + WS_OFF;        // [TILE_K][HDIM]
    float* hs  = smem;                 // [TILE_M][HS_STRIDE] (epilogue; overlaps staging)
    float* w2s = smem + W2_OFF;        // [HDIM*EDIM]
    float* b1s = smem + B1_OFF;        // [HDIM]
    float* b2s = smem + B2_OFF;        // [EDIM]

    const int tid = threadIdx.x;
    const int ty  = tid >> 6;          // 0..3  : row group (16 rows each); warp-uniform
    const int txc = tid & 63;          // 0..63 : col group (cols txc*4..+3)
    const int row0 = blockIdx.x * TILE_M;

    // Small tensors
    for (int i = tid; i < HDIM * EDIM; i += NTHREADS) w2s[i] = W2[i];
    if (tid < HDIM) b1s[tid] = b1[tid];
    if (tid < EDIM) b2s[tid] = b2[tid];

    // Accumulators: 8 row-pairs x 4 cols of packed f32x2 (64 regs)
    // acc[rp][c]: lo = row ty*16+2rp, hi = row ty*16+2rp+1 ; col = txc*4+c
    unsigned long long acc[8][4];
#pragma unroll
    for (int rp = 0; rp < 8; rp++)
#pragma unroll
        for (int c = 0; c < 4; c++) acc[rp][c] = 0ull;

    // ---------------- mainloop: h_acc = x @ W1 ----------------
    for (int k0 = 0; k0 < DDIM; k0 += TILE_K) {
        __syncthreads();   // previous chunk's reads done before overwrite

        // x tile: 64 rows x 32 k -> transposed xs[k][row] (no duplication)
        // lane kk loads column k0+kk for 8 rows (coalesced 128B per row-iter).
        // STS has a 4-way bank conflict (stride 68); costs ~16 extra wavefronts
        // per warp-tile but buys 16B-aligned broadcast LDS.128 in the mainloop.
        {
            int kk = tid & 31;
            int rb = (tid >> 5) * 8;           // 8 warps x 8 rows = 64 rows
            const float* xg = &x[(size_t)(row0 + rb) * DDIM + k0 + kk];
            float xv[8];
#pragma unroll
            for (int i = 0; i < 8; i++) xv[i] = xg[(size_t)i * DDIM];
#pragma unroll
            for (int i = 0; i < 8; i++) xs[kk * XT_STRIDE + rb + i] = xv[i];
        }
        // W1 tile: 32 k-rows x 256 cols, direct (conflict-free float4)
#pragma unroll
        for (int it = 0; it < 8; it++) {
            int v  = tid + NTHREADS * it;      // 0..2047
            int r  = v >> 6;
            int c4 = (v & 63) << 2;
            *reinterpret_cast<float4*>(&ws[r * HDIM + c4]) =
                *reinterpret_cast<const float4*>(&W1[(size_t)(k0 + r) * HDIM + c4]);
        }
        __syncthreads();

#pragma unroll 8
        for (int k = 0; k < TILE_K; k++) {
            // a: 4 broadcast LDS.128 (16B-aligned), each yields 2 row-pairs (N=1)
            const ulonglong2* ap = reinterpret_cast<const ulonglong2*>(
                &xs[k * XT_STRIDE + ty * 16]);
            ulonglong2 a0 = ap[0], a1 = ap[1], a2 = ap[2], a3 = ap[3];
            unsigned long long av[8] = {a0.x, a0.y, a1.x, a1.y,
                                        a2.x, a2.y, a3.x, a3.y};
            // b: one LDS.128 (conflict-free phases), duplicate in-register (alu pipe)
            float4 q0 = *reinterpret_cast<const float4*>(&ws[k * HDIM + txc * 4]);
            unsigned long long bb[4] = {dup2(q0.x), dup2(q0.y), dup2(q0.z), dup2(q0.w)};
#pragma unroll
            for (int rp = 0; rp < 8; rp++)
#pragma unroll
                for (int c = 0; c < 4; c++)
                    fma2(acc[rp][c], av[rp], bb[c]);
        }
    }

    // ---------------- epilogue: relu + bias -> hs ----------------
    __syncthreads();   // all mainloop smem reads complete before hs overwrite
#pragma unroll
    for (int rp = 0; rp < 8; rp++) {
#pragma unroll
        for (int c = 0; c < 4; c++) {
            float2 v = *reinterpret_cast<float2*>(&acc[rp][c]);
            int col = txc * 4 + c;
            float bb1 = b1s[col];
            hs[(ty * 16 + 2 * rp)     * HS_STRIDE + col] = fmaxf(v.x + bb1, 0.0f);
            hs[(ty * 16 + 2 * rp + 1) * HS_STRIDE + col] = fmaxf(v.y + bb1, 0.0f);
        }
    }
    __syncthreads();

    // ---------------- logits = h @ W2 + b2 ; top-2 ; softmax ; scatter ----------------
    {
        const int r = tid >> 2;        // 0..63  row within tile
        const int q = tid & 3;         // quarter of H
        float p[EDIM] = {0.f, 0.f, 0.f, 0.f, 0.f};
        const float* hrow = &hs[r * HS_STRIDE + q * 64];
#pragma unroll 4
        for (int j4 = 0; j4 < 16; j4++) {
            float4 h4 = reinterpret_cast<const float4*>(hrow)[j4];
            float hv[4] = {h4.x, h4.y, h4.z, h4.w};
            int jb = q * 64 + j4 * 4;
#pragma unroll
            for (int u = 0; u < 4; u++) {
                const float* wr = &w2s[(jb + u) * EDIM];
#pragma unroll
                for (int e = 0; e < EDIM; e++) p[e] = fmaf(hv[u], wr[e], p[e]);
            }
        }
        // reduce the 4 partial sums (lanes 4r..4r+3 are in the same warp)
#pragma unroll
        for (int e = 0; e < EDIM; e++) {
            p[e] += __shfl_xor_sync(0xffffffffu, p[e], 1);
            p[e] += __shfl_xor_sync(0xffffffffu, p[e], 2);
        }

        if (q == 0) {
            float l[EDIM];
#pragma unroll
            for (int e = 0; e < EDIM; e++) l[e] = p[e] + b2s[e];

            // top-2, stable tie-break (lower index wins) == jax.lax.top_k
            float v1 = l[0]; int i1 = 0;
            float v2 = -FLT_MAX; int i2 = 0;
#pragma unroll
            for (int e = 1; e < EDIM; e++) {
                if (l[e] > v1)      { v2 = v1; i2 = i1; v1 = l[e]; i1 = e; }
                else if (l[e] > v2) { v2 = l[e]; i2 = e; }
            }
            // softmax over {v1, v2} with max subtraction (matches jax.nn.softmax)
            float e2 = expf(v2 - v1);
            float s  = 1.0f + e2;
            float g1 = 1.0f / s;
            float g2 = e2 / s;

            size_t row = (size_t)(row0 + r);
            size_t gbase = row * EDIM;
#pragma unroll
            for (int e = 0; e < EDIM; e++) {
                float g = 0.0f;
                if (e == i1) g = g1;
                if (e == i2) g = g2;
                out[gbase + e] = g;
            }
            if (write_idx) {
                size_t ibase = (size_t)NB * EDIM + row * 2;
                out[ibase]     = (float)i1;
                out[ibase + 1] = (float)i2;
            }
        }
    }
}

extern "C" void kernel_launch(void* const* d_in, const int* in_sizes, int n_in,
                              void* d_out, int out_size) {
    const float* x  = (const float*)d_in[0];
    const float* W1 = (const float*)d_in[1];
    const float* b1 = (const float*)d_in[2];
    const float* W2 = (const float*)d_in[3];
    const float* b2 = (const float*)d_in[4];
    float* out = (float*)d_out;

    // Output layout confirmed (R10 pass): gates[B,5] then top_idx[B,2] as float32.
    int write_idx = (out_size >= NB * (EDIM + 2)) ? 1 : 0;

    cudaFuncSetAttribute(router_gating_kernel,
                         cudaFuncAttributeMaxDynamicSharedMemorySize, SMEM_BYTES);
    router_gating_kernel<<<NB / TILE_M, NTHREADS, SMEM_BYTES>>>(
        x, W1, b1, W2, b2, out, write_idx);
}